// round 1
// baseline (speedup 1.0000x reference)
#include <cuda_runtime.h>
#include <stdint.h>

#define BATCH   8
#define NNODE   1024
#define CH      256
#define NEDGE   16384
#define BIGN    (BATCH * NNODE)          // 8192
#define WPR     32                       // bitmap words per row (1024/32)

// Scratch (allocation-free rule: __device__ globals)
__device__ unsigned g_adj[BIGN * WPR];   // 1 MB adjacency bitmap
__device__ float    g_dinv[BIGN];        // D^-1/2
__device__ float    g_h[BIGN * CH];      // 8 MB aggregated features

// ---------------------------------------------------------------- zero bitmap
__global__ void k_zero()
{
    int t = blockIdx.x * blockDim.x + threadIdx.x;   // 65536 threads, uint4 each
    ((uint4*)g_adj)[t] = make_uint4(0u, 0u, 0u, 0u);
}

// ---------------------------------------------------------------- edge scatter (dedup via bitmap)
__global__ void k_scatter(const int* __restrict__ ei)
{
    int t = blockIdx.x * blockDim.x + threadIdx.x;   // 0 .. E*B-1, layout [E,B]
    if (t >= NEDGE * BATCH) return;
    int src = ei[t];
    int dst = ei[NEDGE * BATCH + t];
    int b   = t & (BATCH - 1);                       // t % 8
    int row = b * NNODE + src;
    atomicOr(&g_adj[row * WPR + (dst >> 5)], 1u << (dst & 31));
}

// ---------------------------------------------------------------- degree -> dinv
__global__ void k_degree()
{
    int warp = (blockIdx.x * blockDim.x + threadIdx.x) >> 5;
    int lane = threadIdx.x & 31;
    if (warp >= BIGN) return;
    int cnt = __popc(g_adj[warp * WPR + lane]);
    #pragma unroll
    for (int o = 16; o; o >>= 1) cnt += __shfl_down_sync(0xffffffffu, cnt, o);
    if (lane == 0) g_dinv[warp] = rsqrtf((float)(cnt + 1));   // +1 = self loop (eye)
}

// ---------------------------------------------------------------- h = D^-1/2 (A+I) D^-1/2 x
__global__ void __launch_bounds__(256) k_aggregate(const float* __restrict__ x)
{
    __shared__ int   s_list[1024];
    __shared__ int   s_cnt;
    __shared__ float s_dinv_i;

    int row  = blockIdx.x;                 // 0 .. 8191
    int base = (row >> 10) << 10;          // first row of this graph
    int tid  = threadIdx.x;                // channel index 0..255

    if (tid == 0) { s_cnt = 0; s_dinv_i = g_dinv[row]; }
    __syncthreads();

    if (tid < 32) {
        unsigned w = g_adj[row * WPR + tid];
        while (w) {
            int bit = __ffs(w) - 1;
            w &= w - 1;
            int p = atomicAdd(&s_cnt, 1);
            s_list[p] = base + tid * 32 + bit;
        }
    }
    __syncthreads();

    int   cnt    = s_cnt;
    float dinv_i = s_dinv_i;
    // eye term: adj += I on top, so diagonal bit (if present) is also summed below
    float acc = dinv_i * x[row * CH + tid];
    for (int p = 0; p < cnt; p++) {
        int j = s_list[p];
        acc += g_dinv[j] * x[j * CH + tid];
    }
    g_h[row * CH + tid] = dinv_i * acc;
}

// ---------------------------------------------------------------- out = h @ W^T + b  (fp32)
#define BM 64
#define BNT 64
#define BK 16
__global__ void __launch_bounds__(256) k_gemm(const float* __restrict__ Wm,
                                              const float* __restrict__ bias,
                                              float* __restrict__ out)
{
    __shared__ float As[BK][BM];
    __shared__ float Bs[BK][BNT];

    int n0 = blockIdx.x * BNT;
    int m0 = blockIdx.y * BM;
    int tid = threadIdx.x;
    int tx = tid & 15;          // n sub-tile
    int ty = tid >> 4;          // m sub-tile
    int lr = tid >> 2;          // load row 0..63
    int lc = (tid & 3) * 4;     // load col 0,4,8,12

    float acc[4][4] = {};

    for (int k0 = 0; k0 < CH; k0 += BK) {
        // A tile: h[m0+lr][k0+lc..+3]  (row-major, float4)
        float4 a4 = *(const float4*)&g_h[(m0 + lr) * CH + k0 + lc];
        As[lc + 0][lr] = a4.x; As[lc + 1][lr] = a4.y;
        As[lc + 2][lr] = a4.z; As[lc + 3][lr] = a4.w;
        // B tile: W^T[k][n] = W[n][k]; load W[n0+lr][k0+lc..+3]
        float4 b4 = *(const float4*)&Wm[(n0 + lr) * CH + k0 + lc];
        Bs[lc + 0][lr] = b4.x; Bs[lc + 1][lr] = b4.y;
        Bs[lc + 2][lr] = b4.z; Bs[lc + 3][lr] = b4.w;
        __syncthreads();

        #pragma unroll
        for (int k = 0; k < BK; k++) {
            float4 av = *(const float4*)&As[k][ty * 4];
            float4 bv = *(const float4*)&Bs[k][tx * 4];
            float a[4] = {av.x, av.y, av.z, av.w};
            float bb[4] = {bv.x, bv.y, bv.z, bv.w};
            #pragma unroll
            for (int i = 0; i < 4; i++)
                #pragma unroll
                for (int j = 0; j < 4; j++)
                    acc[i][j] += a[i] * bb[j];
        }
        __syncthreads();
    }

    float4 bvec = *(const float4*)&bias[n0 + tx * 4];
    float bb[4] = {bvec.x, bvec.y, bvec.z, bvec.w};
    #pragma unroll
    for (int i = 0; i < 4; i++) {
        int m = m0 + ty * 4 + i;
        float4 o;
        o.x = acc[i][0] + bb[0];
        o.y = acc[i][1] + bb[1];
        o.z = acc[i][2] + bb[2];
        o.w = acc[i][3] + bb[3];
        *(float4*)&out[m * CH + n0 + tx * 4] = o;
    }
}

// ---------------------------------------------------------------- launch
extern "C" void kernel_launch(void* const* d_in, const int* in_sizes, int n_in,
                              void* d_out, int out_size)
{
    const float* x    = (const float*)d_in[0];   // [8,1024,256] f32
    const int*   ei   = (const int*)  d_in[1];   // [2,16384,8] int32
    const float* Wm   = (const float*)d_in[2];   // [256,256] f32
    const float* bias = (const float*)d_in[3];   // [256] f32
    float*       out  = (float*)d_out;           // [8,1024,256] f32

    k_zero<<<(BIGN * WPR / 4 + 255) / 256, 256>>>();
    k_scatter<<<(NEDGE * BATCH + 255) / 256, 256>>>(ei);
    k_degree<<<(BIGN * 32 + 255) / 256, 256>>>();
    k_aggregate<<<BIGN, 256>>>(x);
    k_gemm<<<dim3(CH / BNT, BIGN / BM), 256>>>(Wm, bias, out);
}

// round 3
// speedup vs baseline: 1.4022x; 1.4022x over previous
#include <cuda_runtime.h>
#include <cuda_bf16.h>
#include <stdint.h>

#define BATCH   8
#define NNODE   1024
#define CH      256
#define NEDGE   16384
#define BIGN    (BATCH * NNODE)          // 8192
#define WPR     32                       // bitmap words per row

// ---- scratch (__device__ globals; allocation-free rule) ----
__device__ __align__(128) unsigned        g_adj[BIGN * WPR];   // 1 MB adjacency bitmap
__device__ __align__(128) float           g_dinv[BIGN];
__device__ __align__(128) float           g_xs[BIGN * CH];     // dinv-scaled x (8 MB)
__device__ __align__(128) __nv_bfloat16   g_hhi[BIGN * CH];    // h split hi (4 MB)
__device__ __align__(128) __nv_bfloat16   g_hlo[BIGN * CH];    // h split lo (4 MB)
__device__ __align__(128) __nv_bfloat16   g_whi[CH * CH];
__device__ __align__(128) __nv_bfloat16   g_wlo[CH * CH];

// ================================================================ bitmap zero
__global__ void k_zero() {
    int t = blockIdx.x * blockDim.x + threadIdx.x;
    ((uint4*)g_adj)[t] = make_uint4(0u, 0u, 0u, 0u);
}

// ================================================================ edge scatter (dedup via bitmap)
__global__ void k_scatter(const int* __restrict__ ei) {
    int t = blockIdx.x * blockDim.x + threadIdx.x;
    if (t >= NEDGE * BATCH) return;
    int src = ei[t];
    int dst = ei[NEDGE * BATCH + t];
    int b   = t & (BATCH - 1);
    int row = b * NNODE + src;
    atomicOr(&g_adj[row * WPR + (dst >> 5)], 1u << (dst & 31));
}

// ================================================================ degree -> dinv, x pre-scaled by dinv
__global__ void k_degscale(const float* __restrict__ x) {
    int gw   = (blockIdx.x * blockDim.x + threadIdx.x) >> 5;   // row
    int lane = threadIdx.x & 31;
    if (gw >= BIGN) return;
    int cnt = __popc(g_adj[gw * WPR + lane]);
    cnt = __reduce_add_sync(0xffffffffu, cnt);
    float dinv = rsqrtf((float)(cnt + 1));                     // +1 self loop (eye)
    if (lane == 0) g_dinv[gw] = dinv;
    const float4* xi = (const float4*)(x + gw * CH);
    float4* xo = (float4*)(g_xs + gw * CH);
    #pragma unroll
    for (int i = 0; i < 2; i++) {
        float4 v = xi[lane + i * 32];
        v.x *= dinv; v.y *= dinv; v.z *= dinv; v.w *= dinv;
        xo[lane + i * 32] = v;
    }
}

// ================================================================ W split to bf16 hi/lo
__global__ void k_wsplit(const float* __restrict__ W) {
    int i = blockIdx.x * blockDim.x + threadIdx.x;   // 65536
    float v = W[i];
    __nv_bfloat16 h = __float2bfloat16(v);
    g_whi[i] = h;
    g_wlo[i] = __float2bfloat16(v - __bfloat162float(h));
}

// ================================================================ aggregate: h = D^-1/2 (A+I) D^-1/2 x, split to bf16 hi/lo
__global__ void __launch_bounds__(64) k_aggregate() {
    __shared__ int s_list[1024];
    __shared__ int s_cnt;

    int row  = blockIdx.x;
    int base = row & ~(NNODE - 1);
    int t    = threadIdx.x;           // channel-quad 0..63

    if (t == 0) s_cnt = 0;
    __syncthreads();
    if (t < 32) {
        unsigned w = g_adj[row * WPR + t];
        while (w) {
            int b = __ffs(w) - 1;
            w &= w - 1;
            s_list[atomicAdd(&s_cnt, 1)] = base + t * 32 + b;
        }
    }
    __syncthreads();

    int   cnt    = s_cnt;
    float dinv_i = g_dinv[row];
    const float4* xs4 = (const float4*)g_xs;

    float4 acc = xs4[row * 64 + t];   // eye term (xs already carries dinv)
    int p = 0;
    for (; p + 4 <= cnt; p += 4) {
        int j0 = s_list[p], j1 = s_list[p + 1], j2 = s_list[p + 2], j3 = s_list[p + 3];
        float4 v0 = xs4[j0 * 64 + t], v1 = xs4[j1 * 64 + t];
        float4 v2 = xs4[j2 * 64 + t], v3 = xs4[j3 * 64 + t];
        acc.x += v0.x + v1.x + v2.x + v3.x;
        acc.y += v0.y + v1.y + v2.y + v3.y;
        acc.z += v0.z + v1.z + v2.z + v3.z;
        acc.w += v0.w + v1.w + v2.w + v3.w;
    }
    for (; p < cnt; p++) {
        float4 v = xs4[s_list[p] * 64 + t];
        acc.x += v.x; acc.y += v.y; acc.z += v.z; acc.w += v.w;
    }
    acc.x *= dinv_i; acc.y *= dinv_i; acc.z *= dinv_i; acc.w *= dinv_i;

    __nv_bfloat16 h0 = __float2bfloat16(acc.x), h1 = __float2bfloat16(acc.y);
    __nv_bfloat16 h2 = __float2bfloat16(acc.z), h3 = __float2bfloat16(acc.w);
    __nv_bfloat16 l0 = __float2bfloat16(acc.x - __bfloat162float(h0));
    __nv_bfloat16 l1 = __float2bfloat16(acc.y - __bfloat162float(h1));
    __nv_bfloat16 l2 = __float2bfloat16(acc.z - __bfloat162float(h2));
    __nv_bfloat16 l3 = __float2bfloat16(acc.w - __bfloat162float(h3));

    uint2 hv, lv;
    hv.x = ((uint32_t)__bfloat16_as_ushort(h1) << 16) | __bfloat16_as_ushort(h0);
    hv.y = ((uint32_t)__bfloat16_as_ushort(h3) << 16) | __bfloat16_as_ushort(h2);
    lv.x = ((uint32_t)__bfloat16_as_ushort(l1) << 16) | __bfloat16_as_ushort(l0);
    lv.y = ((uint32_t)__bfloat16_as_ushort(l3) << 16) | __bfloat16_as_ushort(l2);
    *(uint2*)&g_hhi[row * CH + t * 4] = hv;
    *(uint2*)&g_hlo[row * CH + t * 4] = lv;
}

// ================================================================ HMMA GEMM: out = h @ W^T + b
// mma.sync.m16n8k16 bf16, fp32 accum, split-bf16 3-product emulation.
// CTA: 128x128 tile, 8 warps (2 m x 4 n), warp tile 64x32, K=256 fully unrolled by 16.
__device__ __forceinline__ void mma16816(float* c, const uint32_t* a, const uint32_t* b) {
    asm volatile(
        "mma.sync.aligned.m16n8k16.row.col.f32.bf16.bf16.f32 "
        "{%0,%1,%2,%3}, {%4,%5,%6,%7}, {%8,%9}, {%0,%1,%2,%3};"
        : "+f"(c[0]), "+f"(c[1]), "+f"(c[2]), "+f"(c[3])
        : "r"(a[0]), "r"(a[1]), "r"(a[2]), "r"(a[3]), "r"(b[0]), "r"(b[1]));
}

__global__ void __launch_bounds__(256) k_gemm(const float* __restrict__ bias,
                                              float* __restrict__ out)
{
    int tid  = threadIdx.x;
    int wid  = tid >> 5, lane = tid & 31;
    int g    = lane >> 2, tg = lane & 3;          // group / thread-in-group
    int wm   = wid >> 2, wn = wid & 3;
    int m0   = blockIdx.x * 128 + wm * 64;        // warp M origin
    int n0   = blockIdx.y * 128 + wn * 32;        // warp N origin

    float acc[4][4][4];
    #pragma unroll
    for (int i = 0; i < 4; i++)
        #pragma unroll
        for (int j = 0; j < 4; j++)
            #pragma unroll
            for (int q = 0; q < 4; q++) acc[i][j][q] = 0.f;

    #pragma unroll 4
    for (int k0 = 0; k0 < CH; k0 += 16) {
        // ---- B fragments: rows n0+ni*8+g of W, cols k0+2tg (b0) / k0+8+2tg (b1)
        uint32_t bh[4][2], bl[4][2];
        #pragma unroll
        for (int ni = 0; ni < 4; ni++) {
            int nrow = n0 + ni * 8 + g;
            const uint32_t* ph = (const uint32_t*)&g_whi[nrow * CH + k0];
            const uint32_t* pl = (const uint32_t*)&g_wlo[nrow * CH + k0];
            bh[ni][0] = ph[tg]; bh[ni][1] = ph[tg + 4];
            bl[ni][0] = pl[tg]; bl[ni][1] = pl[tg + 4];
        }
        // ---- A fragments: rows m0+mi*16+g (+8), cols k0+2tg / k0+8+2tg
        uint32_t ah[4][4], al[4][4];
        #pragma unroll
        for (int mi = 0; mi < 4; mi++) {
            int r0 = m0 + mi * 16 + g;
            const uint32_t* p0h = (const uint32_t*)&g_hhi[r0 * CH + k0];
            const uint32_t* p1h = (const uint32_t*)&g_hhi[(r0 + 8) * CH + k0];
            const uint32_t* p0l = (const uint32_t*)&g_hlo[r0 * CH + k0];
            const uint32_t* p1l = (const uint32_t*)&g_hlo[(r0 + 8) * CH + k0];
            ah[mi][0] = p0h[tg]; ah[mi][1] = p1h[tg];
            ah[mi][2] = p0h[tg + 4]; ah[mi][3] = p1h[tg + 4];
            al[mi][0] = p0l[tg]; al[mi][1] = p1l[tg];
            al[mi][2] = p0l[tg + 4]; al[mi][3] = p1l[tg + 4];
        }
        // ---- 3-product MMA
        #pragma unroll
        for (int mi = 0; mi < 4; mi++)
            #pragma unroll
            for (int ni = 0; ni < 4; ni++) {
                mma16816(acc[mi][ni], ah[mi], bh[ni]);
                mma16816(acc[mi][ni], ah[mi], bl[ni]);
                mma16816(acc[mi][ni], al[mi], bh[ni]);
            }
    }

    // ---- epilogue: bias + store (float2 pairs)
    #pragma unroll
    for (int ni = 0; ni < 4; ni++) {
        int ncol = n0 + ni * 8 + tg * 2;
        float2 bv = *(const float2*)&bias[ncol];
        #pragma unroll
        for (int mi = 0; mi < 4; mi++) {
            int r = m0 + mi * 16 + g;
            float2 o0, o1;
            o0.x = acc[mi][ni][0] + bv.x;
            o0.y = acc[mi][ni][1] + bv.y;
            o1.x = acc[mi][ni][2] + bv.x;
            o1.y = acc[mi][ni][3] + bv.y;
            *(float2*)&out[r * CH + ncol]       = o0;
            *(float2*)&out[(r + 8) * CH + ncol] = o1;
        }
    }
}

// ================================================================ launch
extern "C" void kernel_launch(void* const* d_in, const int* in_sizes, int n_in,
                              void* d_out, int out_size)
{
    const float* x    = (const float*)d_in[0];   // [8,1024,256] f32
    const int*   ei   = (const int*)  d_in[1];   // [2,16384,8] int32
    const float* Wm   = (const float*)d_in[2];   // [256,256] f32
    const float* bias = (const float*)d_in[3];   // [256] f32
    float*       out  = (float*)d_out;

    k_zero<<<(BIGN * WPR / 4 + 255) / 256, 256>>>();
    k_scatter<<<(NEDGE * BATCH + 255) / 256, 256>>>(ei);
    k_degscale<<<(BIGN * 32 + 255) / 256, 256>>>(x);
    k_wsplit<<<(CH * CH + 255) / 256, 256>>>(Wm);
    k_aggregate<<<BIGN, 64>>>();
    k_gemm<<<dim3(BIGN / 128, CH / 128), 256>>>(bias, out);
}